// round 1
// baseline (speedup 1.0000x reference)
#include <cuda_runtime.h>
#include <math.h>

#define B     64
#define BH    32
#define T     150
#define IN    120
#define HID   1024
#define NB    8
#define ROWS  8192      // HID*NB
#define OUT   35
#define J1    16        // 15 real + 1 pad
#define J2    128
#define VTH   1.0f

// ---------------- device global scratch (no dynamic allocation allowed) ----------------
__device__ float4 g_pk1[ROWS * (J1/2)];      // (w*(1-beta), idx*32) pairs, 2 per float4
__device__ float4 g_pk2[ROWS * (J2/2)];
__device__ float4 g_pk3[ROWS * (J2/2)];
__device__ float  g_rowbias[3][ROWS];
__device__ float  g_rowbeta[3][ROWS];
__device__ float  g_alpha[3][HID];
__device__ float  g_alphar[OUT];
__device__ float  g_xT[T * IN * B];          // [t][k][b]
__device__ float  g_d[3][ROWS * B];          // branch state [row][b]
__device__ float  g_mem[3][HID * B];         // membrane [h][b]
__device__ float  g_spk[3][HID * B];         // spikes transposed [h][b]
__device__ float  g_rd[64 * B * OUT];        // readout partials [chunk][b][o]
__device__ float  g_mr[B * OUT];
__device__ float  g_acc[B * OUT];
__device__ int    g_maskmode;                // 0=u8, 1=i32, 2=f32

// ---------------- preprocessing ----------------

// Detect mask wire dtype: a row of mask2 must contain exactly 128 nonzeros.
__global__ void k_detect(const void* mask2)
{
    if (threadIdx.x != 0 || blockIdx.x != 0) return;
    const unsigned char* p8 = (const unsigned char*)mask2;
    const int*           p32 = (const int*)mask2;
    const float*         pf = (const float*)mask2;
    int c8 = 0, c32 = 0, cf = 0;
    for (int k = 0; k < HID; k++) {
        c8  += (p8[k]  != 0);
        c32 += (p32[k] != 0);
        cf  += (pf[k]  != 0.0f);
    }
    int mode = 0;
    if (c8 == HID / NB) mode = 0;
    else if (c32 == HID / NB) mode = 1;
    else if (cf == HID / NB) mode = 2;
    g_maskmode = mode;
}

__global__ void k_params(const float* tm1, const float* tm2, const float* tm3, const float* tmr)
{
    int i = blockIdx.x * blockDim.x + threadIdx.x;
    if (i < HID)            g_alpha[0][i]         = 1.0f / (1.0f + expf(-tm1[i]));
    else if (i < 2*HID)     g_alpha[1][i - HID]   = 1.0f / (1.0f + expf(-tm2[i - HID]));
    else if (i < 3*HID)     g_alpha[2][i - 2*HID] = 1.0f / (1.0f + expf(-tm3[i - 2*HID]));
    else if (i < 3*HID+OUT) g_alphar[i - 3*HID]   = 1.0f / (1.0f + expf(-tmr[i - 3*HID]));
}

// Build per-row compact (weight,index) pairs with (1-beta) folded into weight & bias.
__global__ void k_compact(int L, const void* mask, const float* __restrict__ w,
                          const float* __restrict__ bias, const float* __restrict__ tau_n,
                          int K, int J)
{
    int r = blockIdx.x * blockDim.x + threadIdx.x;
    if (r >= ROWS) return;
    float beta = 1.0f / (1.0f + expf(-tau_n[r]));
    float sc = 1.0f - beta;
    float2* pk = (L == 0) ? (float2*)g_pk1 : (L == 1) ? (float2*)g_pk2 : (float2*)g_pk3;
    int mode = g_maskmode;
    const unsigned char* m8 = (const unsigned char*)mask;
    const int*           m32 = (const int*)mask;
    const float*         mf = (const float*)mask;
    int j = 0;
    for (int k = 0; k < K; k++) {
        size_t off = (size_t)r * K + k;
        bool on = (mode == 0) ? (m8[off] != 0) : (mode == 1) ? (m32[off] != 0) : (mf[off] != 0.0f);
        if (on && j < J) {
            float2 p;
            p.x = w[off] * sc;
            p.y = __int_as_float(k * 32);   // premultiplied smem word offset
            pk[(size_t)r * J + j] = p;
            j++;
        }
    }
    for (; j < J; j++) {
        float2 p; p.x = 0.0f; p.y = __int_as_float(0);
        pk[(size_t)r * J + j] = p;
    }
    g_rowbias[L][r] = bias[r] * sc;
    g_rowbeta[L][r] = beta;
}

// Transpose x [B,1,T,IN] -> g_xT [t][k][b]
__global__ void k_xT(const float* __restrict__ x)
{
    int i = blockIdx.x * blockDim.x + threadIdx.x;
    if (i >= T * IN * B) return;
    int t = i / (IN * B);
    int rem = i - t * (IN * B);
    int k = rem / B;
    int b = rem - k * B;
    g_xT[i] = x[((size_t)b * T + t) * IN + k];
}

__global__ void k_zero()
{
    int i = blockIdx.x * blockDim.x + threadIdx.x;
    float* df = &g_d[0][0];
    if (i < 3 * ROWS * B) df[i] = 0.0f;
    if (i < 3 * HID * B) (&g_mem[0][0])[i] = 0.0f;
    if (i < B * OUT) { g_mr[i] = 0.0f; g_acc[i] = 0.0f; }
}

// ---------------- per-timestep fused layer kernel ----------------
// grid 128 = 2 batch-halves x 64 row-chunks (16 h each); block 512 = 16 h x 32 b-lanes.
// Warp = one h, lanes = batch -> spike gathers are conflict-free coalesced LDS,
// (w,idx) pair fetches are warp-uniform LDG.128 broadcasts (2 pairs / inst).
template<int K, int J, bool RD>
__global__ void __launch_bounds__(512) k_layer(int L, int t, const float* __restrict__ wr)
{
    extern __shared__ float s[];                 // [K][32] staged inputs (+[16][32] spikes if RD)
    const int tid = threadIdx.x, lane = tid & 31, hl = tid >> 5;
    const int cta = blockIdx.x, half = cta & 1, chunk = cta >> 1;

    const float* inT = (L == 0) ? (g_xT + t * IN * B) : g_spk[L - 1];
    const float4* pk4 = (L == 0) ? g_pk1 : (L == 1) ? g_pk2 : g_pk3;

    // stage this batch-half's inputs into smem: s[k*32 + b_local]
    {
        const float4* src = (const float4*)inT;  // row stride 64 floats = 16 float4
        float4* dst = (float4*)s;
        for (int i = tid; i < K * 8; i += 512) {
            int k = i >> 3, q = i & 7;
            dst[i] = src[k * 16 + half * 8 + q];
        }
    }
    __syncthreads();

    const int h = chunk * 16 + hl;
    const int b = half * 32 + lane;
    float l = 0.0f;

    #pragma unroll
    for (int nb = 0; nb < NB; nb++) {
        int row = h * NB + nb;
        const float4* p = pk4 + row * (J / 2);
        float a0 = g_rowbias[L][row];
        float a1 = 0.0f;
        #pragma unroll 8
        for (int jj = 0; jj < J / 2; jj++) {
            float4 q = p[jj];
            a0 += q.x * s[__float_as_int(q.y) + lane];
            a1 += q.z * s[__float_as_int(q.w) + lane];
        }
        float dd = g_rowbeta[L][row] * g_d[L][row * B + b] + (a0 + a1);
        g_d[L][row * B + b] = dd;
        l += dd;
    }

    float a  = g_alpha[L][h];
    float mo = g_mem[L][h * B + b];
    float sp = (mo > VTH) ? 1.0f : 0.0f;     // previous spike recomputed from stored mem
    float mn = a * mo + (1.0f - a) * l - sp;
    g_mem[L][h * B + b] = mn;
    float sn = (mn > VTH) ? 1.0f : 0.0f;
    g_spk[L][h * B + b] = sn;

    if (RD) {
        float* s3 = s + K * 32;
        s3[hl * 32 + lane] = sn;
        __syncthreads();
        for (int o = hl; o < OUT; o += 16) {
            float r = 0.0f;
            #pragma unroll
            for (int hh = 0; hh < 16; hh++)
                r += wr[o * HID + chunk * 16 + hh] * s3[hh * 32 + lane];
            g_rd[(chunk * B + b) * OUT + o] = r;
        }
    }
}

// mr/acc update: deterministic tree-sum of the 64 chunk partials
__global__ void k_mr(const float* __restrict__ br)
{
    int idx = blockIdx.x * blockDim.x + threadIdx.x;
    if (idx >= B * OUT) return;
    int b = idx / OUT, o = idx - b * OUT;
    float sum = br[o];
    #pragma unroll 8
    for (int c = 0; c < 64; c++) sum += g_rd[(c * B + b) * OUT + o];
    float ar = g_alphar[o];
    float m = ar * g_mr[idx] + (1.0f - ar) * sum;
    g_mr[idx] = m;
    g_acc[idx] += m;
}

__global__ void k_final(float* __restrict__ out)
{
    int b = threadIdx.x;
    if (b >= B) return;
    float v[OUT];
    float mx = -1e30f;
    for (int o = 0; o < OUT; o++) {
        v[o] = g_acc[b * OUT + o] / (float)T;
        mx = fmaxf(mx, v[o]);
    }
    float sum = 0.0f;
    for (int o = 0; o < OUT; o++) sum += expf(v[o] - mx);
    float ls = logf(sum);
    for (int o = 0; o < OUT; o++) out[b * OUT + o] = v[o] - mx - ls;
}

// ---------------- launch ----------------
extern "C" void kernel_launch(void* const* d_in, const int* in_sizes, int n_in,
                              void* d_out, int out_size)
{
    const float* x   = (const float*)d_in[0];
    const float* w1  = (const float*)d_in[1];
    const float* b1  = (const float*)d_in[2];
    const float* tm1 = (const float*)d_in[3];
    const float* tn1 = (const float*)d_in[4];
    const float* w2  = (const float*)d_in[5];
    const float* b2  = (const float*)d_in[6];
    const float* tm2 = (const float*)d_in[7];
    const float* tn2 = (const float*)d_in[8];
    const float* w3  = (const float*)d_in[9];
    const float* b3  = (const float*)d_in[10];
    const float* tm3 = (const float*)d_in[11];
    const float* tn3 = (const float*)d_in[12];
    const float* wr  = (const float*)d_in[13];
    const float* br  = (const float*)d_in[14];
    const float* tmr = (const float*)d_in[15];
    const void*  m1  = d_in[16];
    const void*  m2  = d_in[17];
    const void*  m3  = d_in[18];

    const int SMEM_L23   = HID * 32 * 4;              // 128 KB
    const int SMEM_L23RD = HID * 32 * 4 + 16*32*4;    // +2 KB spikes
    const int SMEM_L1    = IN * 32 * 4;               // 15 KB

    cudaFuncSetAttribute(k_layer<HID, J2, false>, cudaFuncAttributeMaxDynamicSharedMemorySize, SMEM_L23);
    cudaFuncSetAttribute(k_layer<HID, J2, true>,  cudaFuncAttributeMaxDynamicSharedMemorySize, SMEM_L23RD);

    // preprocessing (part of the captured graph; deterministic & cheap)
    k_detect<<<1, 1>>>(m2);
    k_params<<<(3 * HID + OUT + 255) / 256, 256>>>(tm1, tm2, tm3, tmr);
    k_compact<<<ROWS / 256, 256>>>(0, m1, w1, b1, tn1, IN, J1);
    k_compact<<<ROWS / 256, 256>>>(1, m2, w2, b2, tn2, HID, J2);
    k_compact<<<ROWS / 256, 256>>>(2, m3, w3, b3, tn3, HID, J2);
    k_xT<<<(T * IN * B + 255) / 256, 256>>>(x);
    k_zero<<<(3 * ROWS * B + 1023) / 1024, 1024>>>();

    for (int t = 0; t < T; t++) {
        k_layer<IN,  J1, false><<<128, 512, SMEM_L1>>>(0, t, wr);
        k_layer<HID, J2, false><<<128, 512, SMEM_L23>>>(1, t, wr);
        k_layer<HID, J2, true ><<<128, 512, SMEM_L23RD>>>(2, t, wr);
        k_mr<<<(B * OUT + 255) / 256, 256>>>(br);
    }
    k_final<<<1, 64>>>((float*)d_out);
}

// round 2
// speedup vs baseline: 1.2595x; 1.2595x over previous
#include <cuda_runtime.h>
#include <math.h>

#define B     64
#define T     150
#define IN    120
#define HID   1024
#define NB    8
#define ROWS  8192      // HID*NB
#define OUT   35
#define J1    16        // 15 real + 1 pad
#define J2    128
#define VTH   1.0f
#define NCTA  128

// ---------------- device global scratch ----------------
__device__ float4 g_pk1[ROWS * (J1/2)];
__device__ float4 g_pk2[ROWS * (J2/2)];
__device__ float4 g_pk3[ROWS * (J2/2)];
__device__ float  g_rowbias[3][ROWS];
__device__ float  g_rowbeta[3][ROWS];
__device__ float  g_alpha[3][HID];
__device__ float  g_alphar[OUT];
__device__ float  g_xT[T * IN * B];          // [t][k][b]
__device__ float  g_d[3][ROWS * B];
__device__ float  g_mem[3][HID * B];
__device__ float  g_spk[2][HID * B];         // spikes of layers 1,2 (transposed [h][b])
__device__ float  g_rd[64 * B * OUT];        // readout partials [chunk][b][o]
__device__ float  g_mr[B * OUT];
__device__ float  g_acc[B * OUT];
__device__ int    g_maskmode;
__device__ unsigned g_bar_cnt;               // zero-init, self-resetting
__device__ unsigned g_bar_gen;               // monotonically increasing across replays

// ---------------- grid-wide spin barrier ----------------
__device__ __forceinline__ void gsync()
{
    __syncthreads();
    if (threadIdx.x == 0) {
        unsigned gen = *(volatile unsigned*)&g_bar_gen;
        __threadfence();
        unsigned t = atomicAdd(&g_bar_cnt, 1u);
        if (t == NCTA - 1) {
            g_bar_cnt = 0u;
            __threadfence();
            *(volatile unsigned*)&g_bar_gen = gen + 1u;
        } else {
            while (*(volatile unsigned*)&g_bar_gen == gen) { __nanosleep(64); }
        }
    }
    __syncthreads();
}

// ---------------- preprocessing ----------------
// Transpose x [B,1,T,IN] -> g_xT [t][k][b]
__global__ void k_xT(const float* __restrict__ x)
{
    int i = blockIdx.x * blockDim.x + threadIdx.x;
    if (i >= T * IN * B) return;
    int t = i / (IN * B);
    int rem = i - t * (IN * B);
    int k = rem / B;
    int b = rem - k * B;
    g_xT[i] = x[((size_t)b * T + t) * IN + k];
}

__global__ void k_zero()
{
    int i = blockIdx.x * blockDim.x + threadIdx.x;
    if (i < 3 * ROWS * B) (&g_d[0][0])[i] = 0.0f;
    if (i < 3 * HID * B)  (&g_mem[0][0])[i] = 0.0f;
    if (i < B * OUT) { g_mr[i] = 0.0f; g_acc[i] = 0.0f; }
}

// Detect mask wire dtype using one warp (a row of mask2 has exactly 128 nonzeros).
__global__ void k_detect(const void* mask2)
{
    int lane = threadIdx.x;
    if (lane >= 32) return;
    const unsigned char* p8  = (const unsigned char*)mask2;
    const int*           p32 = (const int*)mask2;
    const float*         pf  = (const float*)mask2;
    int c8 = 0, c32 = 0, cf = 0;
    for (int k = lane; k < HID; k += 32) {
        c8  += (p8[k]  != 0);
        c32 += (p32[k] != 0);
        cf  += (pf[k]  != 0.0f);
    }
    #pragma unroll
    for (int o = 16; o > 0; o >>= 1) {
        c8  += __shfl_xor_sync(0xffffffffu, c8,  o);
        c32 += __shfl_xor_sync(0xffffffffu, c32, o);
        cf  += __shfl_xor_sync(0xffffffffu, cf,  o);
    }
    if (lane == 0) {
        int mode = 0;
        if (c8 == HID / NB) mode = 0;
        else if (c32 == HID / NB) mode = 1;
        else if (cf == HID / NB) mode = 2;
        g_maskmode = mode;
    }
}

__global__ void k_params(const float* tm1, const float* tm2, const float* tm3, const float* tmr)
{
    int i = blockIdx.x * blockDim.x + threadIdx.x;
    if (i < HID)            g_alpha[0][i]         = 1.0f / (1.0f + expf(-tm1[i]));
    else if (i < 2*HID)     g_alpha[1][i - HID]   = 1.0f / (1.0f + expf(-tm2[i - HID]));
    else if (i < 3*HID)     g_alpha[2][i - 2*HID] = 1.0f / (1.0f + expf(-tm3[i - 2*HID]));
    else if (i < 3*HID+OUT) g_alphar[i - 3*HID]   = 1.0f / (1.0f + expf(-tmr[i - 3*HID]));
}

__device__ __forceinline__ bool mask_test(const void* mask, size_t off, int mode)
{
    if (mode == 0) return ((const unsigned char*)mask)[off] != 0;
    if (mode == 1) return ((const int*)mask)[off] != 0;
    return ((const float*)mask)[off] != 0.0f;
}

// Fused warp-per-row ballot compaction for all 3 layers.
__global__ void k_compact_all(const void* m1, const float* w1, const float* b1, const float* tn1,
                              const void* m2, const float* w2, const float* b2, const float* tn2,
                              const void* m3, const float* w3, const float* b3, const float* tn3)
{
    int gw = (blockIdx.x * blockDim.x + threadIdx.x) >> 5;
    int lane = threadIdx.x & 31;
    if (gw >= 3 * ROWS) return;
    int L = gw / ROWS;
    int r = gw - L * ROWS;

    const void*  mask = (L == 0) ? m1 : (L == 1) ? m2 : m3;
    const float* w    = (L == 0) ? w1 : (L == 1) ? w2 : w3;
    const float* bias = (L == 0) ? b1 : (L == 1) ? b2 : b3;
    const float* tn   = (L == 0) ? tn1 : (L == 1) ? tn2 : tn3;
    float2* pk = (L == 0) ? (float2*)g_pk1 : (L == 1) ? (float2*)g_pk2 : (float2*)g_pk3;
    const int K = (L == 0) ? IN : HID;
    const int J = (L == 0) ? J1 : J2;

    float beta = 1.0f / (1.0f + expf(-tn[r]));
    float sc = 1.0f - beta;
    int mode = g_maskmode;

    int j = 0;
    for (int base = 0; base < K; base += 32) {
        int k = base + lane;
        bool on = (k < K) && mask_test(mask, (size_t)r * K + k, mode);
        unsigned bal = __ballot_sync(0xffffffffu, on);
        int pre = __popc(bal & ((1u << lane) - 1u));
        if (on && (j + pre) < J) {
            float2 p;
            p.x = w[(size_t)r * K + k] * sc;
            p.y = __int_as_float(k * 32);
            pk[(size_t)r * J + j + pre] = p;
        }
        j += __popc(bal);
    }
    if (j > J) j = J;
    for (int jj = j + lane; jj < J; jj += 32) {
        float2 p; p.x = 0.0f; p.y = __int_as_float(0);
        pk[(size_t)r * J + jj] = p;
    }
    if (lane == 0) {
        g_rowbias[L][r] = bias[r] * sc;
        g_rowbeta[L][r] = beta;
    }
}

// ---------------- persistent main kernel ----------------
// grid 128 = 2 batch-halves x 64 row-chunks (16 h each); block 512 = 16 h warps x 32 b-lanes.
template<int K, int J, bool RD>
__device__ __forceinline__ void layer_step(
    int L, const float* __restrict__ inT, const float4* __restrict__ pk4,
    int half, int chunk, int hl, int lane, const float* __restrict__ wr, float* s)
{
    const int tid = (hl << 5) | lane;
    // stage this batch-half's inputs into smem: s[k*32 + b_local]
    {
        const float4* src = (const float4*)inT;  // row stride 64 floats = 16 float4
        float4* dst = (float4*)s;
        for (int i = tid; i < K * 8; i += 512) {
            int k = i >> 3, q = i & 7;
            dst[i] = src[k * 16 + half * 8 + q];
        }
    }
    __syncthreads();

    const int h = chunk * 16 + hl;
    const int b = half * 32 + lane;
    float l = 0.0f;

    #pragma unroll
    for (int nb = 0; nb < NB; nb++) {
        int row = h * NB + nb;
        const float4* p = pk4 + row * (J / 2);
        float a0 = g_rowbias[L][row];
        float a1 = 0.0f;
        #pragma unroll 8
        for (int jj = 0; jj < J / 2; jj++) {
            float4 q = p[jj];
            a0 += q.x * s[__float_as_int(q.y) + lane];
            a1 += q.z * s[__float_as_int(q.w) + lane];
        }
        float dd = g_rowbeta[L][row] * g_d[L][row * B + b] + (a0 + a1);
        g_d[L][row * B + b] = dd;
        l += dd;
    }

    float a  = g_alpha[L][h];
    float mo = g_mem[L][h * B + b];
    float sp = (mo > VTH) ? 1.0f : 0.0f;     // previous spike recomputed from stored mem
    float mn = a * mo + (1.0f - a) * l - sp;
    g_mem[L][h * B + b] = mn;
    float sn = (mn > VTH) ? 1.0f : 0.0f;
    if (L < 2) g_spk[L][h * B + b] = sn;

    if (RD) {
        float* s3 = s + K * 32;
        s3[hl * 32 + lane] = sn;
        __syncthreads();
        for (int o = hl; o < OUT; o += 16) {
            float r = 0.0f;
            #pragma unroll
            for (int hh = 0; hh < 16; hh++)
                r += wr[o * HID + chunk * 16 + hh] * s3[hh * 32 + lane];
            g_rd[(chunk * B + b) * OUT + o] = r;
        }
    }
}

__device__ __forceinline__ void mr_update(const float* __restrict__ br, int tid)
{
    for (int idx = tid; idx < B * OUT; idx += 512) {
        int b = idx / OUT, o = idx - b * OUT;
        float sum = br[o];
        #pragma unroll 8
        for (int c = 0; c < 64; c++) sum += g_rd[(c * B + b) * OUT + o];
        float ar = g_alphar[o];
        float m = ar * g_mr[idx] + (1.0f - ar) * sum;
        g_mr[idx] = m;
        g_acc[idx] += m;
    }
}

__global__ void __launch_bounds__(512, 1) k_main(const float* __restrict__ wr,
                                                 const float* __restrict__ br,
                                                 float* __restrict__ out)
{
    extern __shared__ float s[];
    const int tid = threadIdx.x, lane = tid & 31, hl = tid >> 5;
    const int cta = blockIdx.x, half = cta & 1, chunk = cta >> 1;

    for (int t = 0; t < T; t++) {
        layer_step<IN, J1, false>(0, g_xT + t * IN * B, g_pk1, half, chunk, hl, lane, wr, s);
        if (cta == 0 && t > 0) mr_update(br, tid);   // consume step t-1 readout
        gsync();
        layer_step<HID, J2, false>(1, g_spk[0], g_pk2, half, chunk, hl, lane, wr, s);
        gsync();
        layer_step<HID, J2, true>(2, g_spk[1], g_pk3, half, chunk, hl, lane, wr, s);
        gsync();
    }

    if (cta == 0) {
        mr_update(br, tid);                          // step T-1
        __syncthreads();
        if (tid < B) {
            int b = tid;
            float v[OUT];
            float mx = -1e30f;
            #pragma unroll
            for (int o = 0; o < OUT; o++) {
                v[o] = g_acc[b * OUT + o] / (float)T;
                mx = fmaxf(mx, v[o]);
            }
            float sum = 0.0f;
            #pragma unroll
            for (int o = 0; o < OUT; o++) sum += expf(v[o] - mx);
            float ls = logf(sum);
            #pragma unroll
            for (int o = 0; o < OUT; o++) out[b * OUT + o] = v[o] - mx - ls;
        }
    }
}

// ---------------- launch ----------------
extern "C" void kernel_launch(void* const* d_in, const int* in_sizes, int n_in,
                              void* d_out, int out_size)
{
    const float* x   = (const float*)d_in[0];
    const float* w1  = (const float*)d_in[1];
    const float* b1  = (const float*)d_in[2];
    const float* tm1 = (const float*)d_in[3];
    const float* tn1 = (const float*)d_in[4];
    const float* w2  = (const float*)d_in[5];
    const float* b2  = (const float*)d_in[6];
    const float* tm2 = (const float*)d_in[7];
    const float* tn2 = (const float*)d_in[8];
    const float* w3  = (const float*)d_in[9];
    const float* b3  = (const float*)d_in[10];
    const float* tm3 = (const float*)d_in[11];
    const float* tn3 = (const float*)d_in[12];
    const float* wr  = (const float*)d_in[13];
    const float* br  = (const float*)d_in[14];
    const float* tmr = (const float*)d_in[15];
    const void*  m1  = d_in[16];
    const void*  m2  = d_in[17];
    const void*  m3  = d_in[18];

    const int SMEM_MAIN = HID * 32 * 4 + 16 * 32 * 4;  // 128KB staging + 2KB spikes
    static int s_attr_done = 0;
    (void)s_attr_done;
    cudaFuncSetAttribute(k_main, cudaFuncAttributeMaxDynamicSharedMemorySize, SMEM_MAIN);

    // launch order chosen so ncu (-s 5 -c 1) captures k_main
    k_xT<<<(T * IN * B + 255) / 256, 256>>>(x);
    k_zero<<<(3 * ROWS * B + 1023) / 1024, 1024>>>();
    k_detect<<<1, 32>>>(m2);
    k_params<<<(3 * HID + OUT + 255) / 256, 256>>>(tm1, tm2, tm3, tmr);
    k_compact_all<<<(3 * ROWS * 32 + 255) / 256, 256>>>(m1, w1, b1, tn1,
                                                        m2, w2, b2, tn2,
                                                        m3, w3, b3, tn3);
    k_main<<<NCTA, 512, SMEM_MAIN>>>(wr, br, (float*)d_out);
}

// round 3
// speedup vs baseline: 2.4742x; 1.9645x over previous
#include <cuda_runtime.h>
#include <math.h>
#include <stdint.h>

#define B     64
#define T     150
#define IN    120
#define HID   1024
#define NB    8
#define ROWS  8192      // HID*NB
#define OUT   35
#define J1    16        // 15 real + 1 pad
#define J2    128
#define VTH   1.0f
#define NCTA  128

// ---------------- device global scratch ----------------
__device__ float4 g_pk1[ROWS * (J1/2)];      // (w*(1-beta), byteoff) pairs, 2/float4
__device__ float4 g_pk2[ROWS * (J2/2)];
__device__ float4 g_pk3[ROWS * (J2/2)];
__device__ float  g_rowbias[3][ROWS];
__device__ float  g_rowbeta[3][ROWS];
__device__ float  g_alpha[3][HID];
__device__ float  g_alphar[OUT];
__device__ float  g_xT[T * 2 * IN * 32];     // [t][half][k][lane]
__device__ float  g_d[3][ROWS * B];          // [row][b]   (CTA-owned slices)
__device__ float  g_mem[3][HID * B];         // [h][b]     (CTA-owned slices)
__device__ float  g_spk[2][2 * HID * 32];    // [L][half][h][lane]  (cross-CTA)
__device__ float  g_rd[64 * B * OUT];        // readout partials [chunk][b][o]
__device__ float  g_mr[B * OUT];
__device__ float  g_acc[B * OUT];
__device__ int    g_maskmode;
__device__ unsigned g_bar_cnt;               // zeroed by k_zero each replay

// ---------------- async-copy + memory-order helpers ----------------
__device__ __forceinline__ void cp16(uint32_t dst, const void* src) {
    asm volatile("cp.async.cg.shared.global [%0], [%1], 16;" :: "r"(dst), "l"(src));
}
#define CP_COMMIT() asm volatile("cp.async.commit_group;" ::: "memory")
#define CP_WAIT0()  asm volatile("cp.async.wait_group 0;" ::: "memory")
#define CP_WAIT1()  asm volatile("cp.async.wait_group 1;" ::: "memory")

__device__ __forceinline__ float ldcv(const float* p) {
    float v; asm volatile("ld.global.cv.f32 %0, [%1];" : "=f"(v) : "l"(p)); return v;
}

// grid barrier: monotonic counter, release-arrive / acquire-poll
__device__ __forceinline__ void gsync(unsigned target) {
    __syncthreads();
    if (threadIdx.x == 0) {
        asm volatile("red.release.gpu.global.add.u32 [%0], %1;"
                     :: "l"(&g_bar_cnt), "r"(1u) : "memory");
        unsigned v;
        do {
            asm volatile("ld.acquire.gpu.global.u32 %0, [%1];"
                         : "=r"(v) : "l"(&g_bar_cnt) : "memory");
        } while (v < target);
    }
    __syncthreads();
}

// ---------------- preprocessing kernels ----------------
__global__ void k_xT(const float* __restrict__ x)
{
    int i = blockIdx.x * blockDim.x + threadIdx.x;
    if (i >= T * IN * B) return;
    int t = i / (IN * B);
    int rem = i - t * (IN * B);
    int k = rem / B;
    int b = rem - k * B;
    int half = b >> 5, lane = b & 31;
    g_xT[((t * 2 + half) * IN + k) * 32 + lane] = x[((size_t)b * T + t) * IN + k];
}

__global__ void k_zero()
{
    int i = blockIdx.x * blockDim.x + threadIdx.x;
    if (i == 0) g_bar_cnt = 0u;
    if (i < 3 * ROWS * B) (&g_d[0][0])[i] = 0.0f;
    if (i < 3 * HID * B)  (&g_mem[0][0])[i] = 0.0f;
    if (i < B * OUT) { g_mr[i] = 0.0f; g_acc[i] = 0.0f; }
}

__global__ void k_detect(const void* mask2)
{
    int lane = threadIdx.x;
    if (lane >= 32) return;
    const unsigned char* p8  = (const unsigned char*)mask2;
    const int*           p32 = (const int*)mask2;
    const float*         pf  = (const float*)mask2;
    int c8 = 0, c32 = 0, cf = 0;
    for (int k = lane; k < HID; k += 32) {
        c8  += (p8[k]  != 0);
        c32 += (p32[k] != 0);
        cf  += (pf[k]  != 0.0f);
    }
    #pragma unroll
    for (int o = 16; o > 0; o >>= 1) {
        c8  += __shfl_xor_sync(0xffffffffu, c8,  o);
        c32 += __shfl_xor_sync(0xffffffffu, c32, o);
        cf  += __shfl_xor_sync(0xffffffffu, cf,  o);
    }
    if (lane == 0) {
        int mode = 0;
        if (c8 == HID / NB) mode = 0;
        else if (c32 == HID / NB) mode = 1;
        else if (cf == HID / NB) mode = 2;
        g_maskmode = mode;
    }
}

__global__ void k_params(const float* tm1, const float* tm2, const float* tm3, const float* tmr)
{
    int i = blockIdx.x * blockDim.x + threadIdx.x;
    if (i < HID)            g_alpha[0][i]         = 1.0f / (1.0f + expf(-tm1[i]));
    else if (i < 2*HID)     g_alpha[1][i - HID]   = 1.0f / (1.0f + expf(-tm2[i - HID]));
    else if (i < 3*HID)     g_alpha[2][i - 2*HID] = 1.0f / (1.0f + expf(-tm3[i - 2*HID]));
    else if (i < 3*HID+OUT) g_alphar[i - 3*HID]   = 1.0f / (1.0f + expf(-tmr[i - 3*HID]));
}

__device__ __forceinline__ bool mask_test(const void* mask, size_t off, int mode)
{
    if (mode == 0) return ((const unsigned char*)mask)[off] != 0;
    if (mode == 1) return ((const int*)mask)[off] != 0;
    return ((const float*)mask)[off] != 0.0f;
}

// warp-per-row ballot compaction; index stored as smem BYTE offset (k*128)
__global__ void k_compact_all(const void* m1, const float* w1, const float* b1, const float* tn1,
                              const void* m2, const float* w2, const float* b2, const float* tn2,
                              const void* m3, const float* w3, const float* b3, const float* tn3)
{
    int gw = (blockIdx.x * blockDim.x + threadIdx.x) >> 5;
    int lane = threadIdx.x & 31;
    if (gw >= 3 * ROWS) return;
    int L = gw / ROWS;
    int r = gw - L * ROWS;

    const void*  mask = (L == 0) ? m1 : (L == 1) ? m2 : m3;
    const float* w    = (L == 0) ? w1 : (L == 1) ? w2 : w3;
    const float* bias = (L == 0) ? b1 : (L == 1) ? b2 : b3;
    const float* tn   = (L == 0) ? tn1 : (L == 1) ? tn2 : tn3;
    float2* pk = (L == 0) ? (float2*)g_pk1 : (L == 1) ? (float2*)g_pk2 : (float2*)g_pk3;
    const int K = (L == 0) ? IN : HID;
    const int J = (L == 0) ? J1 : J2;

    float beta = 1.0f / (1.0f + expf(-tn[r]));
    float sc = 1.0f - beta;
    int mode = g_maskmode;

    int j = 0;
    for (int base = 0; base < K; base += 32) {
        int k = base + lane;
        bool on = (k < K) && mask_test(mask, (size_t)r * K + k, mode);
        unsigned bal = __ballot_sync(0xffffffffu, on);
        int pre = __popc(bal & ((1u << lane) - 1u));
        if (on && (j + pre) < J) {
            float2 p;
            p.x = w[(size_t)r * K + k] * sc;
            p.y = __int_as_float(k * 128);      // byte offset into s_in row block
            pk[(size_t)r * J + j + pre] = p;
        }
        j += __popc(bal);
    }
    if (j > J) j = J;
    for (int jj = j + lane; jj < J; jj += 32) {
        float2 p; p.x = 0.0f; p.y = __int_as_float(0);
        pk[(size_t)r * J + jj] = p;
    }
    if (lane == 0) {
        g_rowbias[L][r] = bias[r] * sc;
        g_rowbeta[L][r] = beta;
    }
}

// ---------------- persistent main kernel ----------------
// grid 128 = 2 halves x 64 chunks(16 h); block 512 = 16 h-warps x 32 batch lanes.
// smem: s_in 128KB staged inputs | s_pk 2x16KB pk double buffer | s_rd 2KB

__device__ __forceinline__ void pk_pf(uint32_t dst, const float4* src, int lane, int nf4)
{
    if (lane < nf4)      cp16(dst + lane * 16,       src + lane);
    if (lane + 32 < nf4) cp16(dst + 512 + lane * 16, src + 32 + lane);
}

template<int K, int J, bool RD>
__device__ __forceinline__ void layer_step(
    int L, const float* __restrict__ inHalf, const float4* __restrict__ pk4,
    int half, int chunk, int hl, int lane, const float* __restrict__ wr,
    float* s_in, const float4* s_pkg, uint32_t s_in_u32, uint32_t s_pk_u32, float* s_rd)
{
    const int tid = (hl << 5) | lane;
    constexpr int nf4 = J / 2;
    const int row0 = (chunk * 16 + hl) * NB;

    __syncthreads();   // protect s_in reuse from previous phase

    // stage inputs: K*32 floats contiguous, via L1-bypassing async copy
    for (int i = tid; i < K * 8; i += 512)
        cp16(s_in_u32 + i * 16, (const float4*)inHalf + i);

    const uint32_t buf0 = s_pk_u32 + hl * 1024;
    const uint32_t buf1 = s_pk_u32 + 16384 + hl * 1024;
    pk_pf(buf0, pk4 + (size_t)row0 * nf4, lane, nf4);
    CP_COMMIT();                                   // g0 = staging + pf(0)
    pk_pf(buf1, pk4 + (size_t)(row0 + 1) * nf4, lane, nf4);
    CP_COMMIT();                                   // g1 = pf(1)
    CP_WAIT1();                                    // g0 complete
    __syncthreads();                               // all staging visible

    const int h = chunk * 16 + hl;
    const int b = half * 32 + lane;
    const char* sb = (const char*)s_in + lane * 4;
    float l = 0.0f;

    #pragma unroll
    for (int nb = 0; nb < NB; nb++) {
        const int row = row0 + nb;
        const float4* p = s_pkg + (nb & 1) * 1024 + hl * 64;
        float a0 = g_rowbias[L][row], a1 = 0.0f, a2 = 0.0f, a3 = 0.0f;
        #pragma unroll
        for (int jj = 0; jj < nf4; jj += 2) {
            float4 q = p[jj];
            a0 += q.x * *(const float*)(sb + __float_as_int(q.y));
            a1 += q.z * *(const float*)(sb + __float_as_int(q.w));
            float4 r2 = p[jj + 1];
            a2 += r2.x * *(const float*)(sb + __float_as_int(r2.y));
            a3 += r2.z * *(const float*)(sb + __float_as_int(r2.w));
        }
        float dd = g_rowbeta[L][row] * g_d[L][row * B + b] + ((a0 + a2) + (a1 + a3));
        g_d[L][row * B + b] = dd;
        l += dd;
        if (nb + 2 < NB) {
            pk_pf((nb & 1) ? buf1 : buf0, pk4 + (size_t)(row0 + nb + 2) * nf4, lane, nf4);
            CP_COMMIT();
        }
        if (nb + 1 < NB) { if (nb + 2 < NB) CP_WAIT1(); else CP_WAIT0(); }
    }

    float a  = g_alpha[L][h];
    float mo = g_mem[L][h * B + b];
    float sp = (mo > VTH) ? 1.0f : 0.0f;
    float mn = a * mo + (1.0f - a) * l - sp;
    g_mem[L][h * B + b] = mn;
    float sn = (mn > VTH) ? 1.0f : 0.0f;
    if (!RD) g_spk[L][(half * HID + h) * 32 + lane] = sn;

    if (RD) {
        s_rd[hl * 32 + lane] = sn;
        __syncthreads();
        for (int o = hl; o < OUT; o += 16) {
            float r = 0.0f;
            #pragma unroll
            for (int hh = 0; hh < 16; hh++)
                r += wr[o * HID + chunk * 16 + hh] * s_rd[hh * 32 + lane];
            g_rd[(chunk * B + b) * OUT + o] = r;
        }
    }
}

__device__ __forceinline__ void mr_update_dist(const float* __restrict__ br, int cta, int tid)
{
    int idx = cta * 512 + tid;
    if (idx < B * OUT) {
        int b = idx / OUT, o = idx - b * OUT;
        float sum = br[o];
        #pragma unroll 8
        for (int c = 0; c < 64; c++) sum += ldcv(&g_rd[(c * B + b) * OUT + o]);
        float ar = g_alphar[o];
        float m = ar * g_mr[idx] + (1.0f - ar) * sum;
        g_mr[idx] = m;
        g_acc[idx] += m;
    }
}

__global__ void __launch_bounds__(512, 1) k_main(const float* __restrict__ wr,
                                                 const float* __restrict__ br,
                                                 float* __restrict__ out)
{
    extern __shared__ float s[];
    float*  s_in  = s;                         // 32768 floats
    float4* s_pkg = (float4*)(s + 32768);      // 2048 float4 (2 x 16KB)
    float*  s_rd  = s + 32768 + 8192;          // 512 floats
    const uint32_t s_in_u32 = (uint32_t)__cvta_generic_to_shared(s_in);
    const uint32_t s_pk_u32 = (uint32_t)__cvta_generic_to_shared(s_pkg);

    const int tid = threadIdx.x, lane = tid & 31, hl = tid >> 5;
    const int cta = blockIdx.x, half = cta & 1, chunk = cta >> 1;
    unsigned nbar = 0;

    // prologue: L1(0)
    layer_step<IN, J1, false>(0, g_xT + (0 * 2 + half) * IN * 32, g_pk1,
                              half, chunk, hl, lane, wr, s_in, s_pkg, s_in_u32, s_pk_u32, s_rd);
    gsync(NCTA * (++nbar));

    for (int t = 0; t < T; t++) {
        // epoch A: L2(t) [+ consume readout of t-1]
        layer_step<HID, J2, false>(1, g_spk[0] + half * HID * 32, g_pk2,
                                   half, chunk, hl, lane, wr, s_in, s_pkg, s_in_u32, s_pk_u32, s_rd);
        if (t > 0) mr_update_dist(br, cta, tid);
        gsync(NCTA * (++nbar));
        // epoch B: L3(t) + L1(t+1)
        layer_step<HID, J2, true>(2, g_spk[1] + half * HID * 32, g_pk3,
                                  half, chunk, hl, lane, wr, s_in, s_pkg, s_in_u32, s_pk_u32, s_rd);
        if (t + 1 < T)
            layer_step<IN, J1, false>(0, g_xT + ((t + 1) * 2 + half) * IN * 32, g_pk1,
                                      half, chunk, hl, lane, wr, s_in, s_pkg, s_in_u32, s_pk_u32, s_rd);
        gsync(NCTA * (++nbar));
    }

    mr_update_dist(br, cta, tid);   // step T-1
    gsync(NCTA * (++nbar));

    if (cta == 0 && tid < B) {
        int b = tid;
        float v[OUT];
        float mx = -1e30f;
        #pragma unroll
        for (int o = 0; o < OUT; o++) {
            v[o] = ldcv(&g_acc[b * OUT + o]) / (float)T;
            mx = fmaxf(mx, v[o]);
        }
        float sum = 0.0f;
        #pragma unroll
        for (int o = 0; o < OUT; o++) sum += expf(v[o] - mx);
        float ls = logf(sum);
        #pragma unroll
        for (int o = 0; o < OUT; o++) out[b * OUT + o] = v[o] - mx - ls;
    }
}

// ---------------- launch ----------------
extern "C" void kernel_launch(void* const* d_in, const int* in_sizes, int n_in,
                              void* d_out, int out_size)
{
    const float* x   = (const float*)d_in[0];
    const float* w1  = (const float*)d_in[1];
    const float* b1  = (const float*)d_in[2];
    const float* tm1 = (const float*)d_in[3];
    const float* tn1 = (const float*)d_in[4];
    const float* w2  = (const float*)d_in[5];
    const float* b2  = (const float*)d_in[6];
    const float* tm2 = (const float*)d_in[7];
    const float* tn2 = (const float*)d_in[8];
    const float* w3  = (const float*)d_in[9];
    const float* b3  = (const float*)d_in[10];
    const float* tm3 = (const float*)d_in[11];
    const float* tn3 = (const float*)d_in[12];
    const float* wr  = (const float*)d_in[13];
    const float* br  = (const float*)d_in[14];
    const float* tmr = (const float*)d_in[15];
    const void*  m1  = d_in[16];
    const void*  m2  = d_in[17];
    const void*  m3  = d_in[18];

    const int SMEM_MAIN = (32768 + 8192 + 512) * 4;   // 165888 B
    cudaFuncSetAttribute(k_main, cudaFuncAttributeMaxDynamicSharedMemorySize, SMEM_MAIN);

    k_xT<<<(T * IN * B + 255) / 256, 256>>>(x);
    k_zero<<<(3 * ROWS * B + 1023) / 1024, 1024>>>();
    k_detect<<<1, 32>>>(m2);
    k_params<<<(3 * HID + OUT + 255) / 256, 256>>>(tm1, tm2, tm3, tmr);
    k_compact_all<<<(3 * ROWS * 32 + 255) / 256, 256>>>(m1, w1, b1, tn1,
                                                        m2, w2, b2, tn2,
                                                        m3, w3, b3, tn3);
    k_main<<<NCTA, 512, SMEM_MAIN>>>(wr, br, (float*)d_out);
}

// round 4
// speedup vs baseline: 3.7146x; 1.5013x over previous
#include <cuda_runtime.h>
#include <math.h>
#include <stdint.h>

#define B     64
#define T     150
#define IN    120
#define HID   1024
#define NB    8
#define ROWS  8192
#define OUT   35
#define J1    16
#define J2    128
#define VTH   1.0f
#define NCTA  128
#define HPC   8          // h per CTA

// ---------------- device global scratch ----------------
__device__ float4  g_pk1[ROWS * (J1/2)];
__device__ float4  g_pk2[ROWS * (J2/2)];
__device__ float4  g_pk3[ROWS * (J2/2)];
__device__ float   g_rowbias[3][ROWS];
__device__ float   g_rowbeta[3][ROWS];
__device__ float   g_alpha[3][HID];
__device__ float   g_alphar[OUT];
__device__ float2  g_xT[T * IN * 32];       // [t][k][lane] = x(b=2lane, 2lane+1)
__device__ float2  g_d[3][ROWS * 32];       // [row][lane]
__device__ float2  g_mem[3][HID * 32];      // [h][lane]
__device__ unsigned g_spkb[2][HID * 32];    // packed bf16x2 spikes [h][lane]
__device__ float   g_rd[NCTA * OUT * B];    // [cta][o*64+b]
__device__ float   g_mr[OUT * B];           // [o*64+b]
__device__ float   g_acc[OUT * B];
__device__ int     g_maskmode;
__device__ unsigned g_bar_cnt;

// ---------------- helpers ----------------
__device__ __forceinline__ void cp16(uint32_t dst, const void* src) {
    asm volatile("cp.async.cg.shared.global [%0], [%1], 16;" :: "r"(dst), "l"(src));
}
#define CP_COMMIT() asm volatile("cp.async.commit_group;" ::: "memory")
#define CP_WAIT0()  asm volatile("cp.async.wait_group 0;" ::: "memory")
#define CP_WAIT1()  asm volatile("cp.async.wait_group 1;" ::: "memory")

__device__ __forceinline__ float ldcv(const float* p) {
    float v; asm volatile("ld.global.cv.f32 %0, [%1];" : "=f"(v) : "l"(p)); return v;
}

__device__ __forceinline__ void gsync(unsigned target) {
    __syncthreads();
    if (threadIdx.x == 0) {
        asm volatile("red.release.gpu.global.add.u32 [%0], %1;"
                     :: "l"(&g_bar_cnt), "r"(1u) : "memory");
        unsigned v;
        do {
            asm volatile("ld.acquire.gpu.global.u32 %0, [%1];"
                         : "=r"(v) : "l"(&g_bar_cnt) : "memory");
        } while (v < target);
    }
    __syncthreads();
}

// ---------------- preprocessing (2 kernels) ----------------
__global__ void k_pre(const float* __restrict__ x,
                      const float* tm1, const float* tm2, const float* tm3, const float* tmr,
                      const void* mask2)
{
    int i = blockIdx.x * blockDim.x + threadIdx.x;
    if (i == 0) g_bar_cnt = 0u;
    if (i < 3 * ROWS * 32) (&g_d[0][0])[i] = make_float2(0.f, 0.f);
    if (i < 3 * HID * 32)  (&g_mem[0][0])[i] = make_float2(0.f, 0.f);
    if (i < OUT * B) { g_mr[i] = 0.f; g_acc[i] = 0.f; }
    if (i < T * IN * 64) {
        int c = i & 1, lane = (i >> 1) & 31, tk = i >> 6;
        int k = tk % IN, t = tk / IN;
        int b = 2 * lane + c;
        ((float*)g_xT)[i] = x[((size_t)b * T + t) * IN + k];
    }
    if (i < HID)            g_alpha[0][i]         = 1.0f / (1.0f + expf(-tm1[i]));
    else if (i < 2*HID)     g_alpha[1][i - HID]   = 1.0f / (1.0f + expf(-tm2[i - HID]));
    else if (i < 3*HID)     g_alpha[2][i - 2*HID] = 1.0f / (1.0f + expf(-tm3[i - 2*HID]));
    else if (i < 3*HID+OUT) g_alphar[i - 3*HID]   = 1.0f / (1.0f + expf(-tmr[i - 3*HID]));
    if (blockIdx.x == 0 && threadIdx.x < 32) {
        int lane = threadIdx.x;
        const unsigned char* p8  = (const unsigned char*)mask2;
        const int*           p32 = (const int*)mask2;
        const float*         pf  = (const float*)mask2;
        int c8 = 0, c32 = 0, cf = 0;
        for (int k = lane; k < HID; k += 32) {
            c8  += (p8[k]  != 0);
            c32 += (p32[k] != 0);
            cf  += (pf[k]  != 0.0f);
        }
        #pragma unroll
        for (int o = 16; o > 0; o >>= 1) {
            c8  += __shfl_xor_sync(0xffffffffu, c8,  o);
            c32 += __shfl_xor_sync(0xffffffffu, c32, o);
            cf  += __shfl_xor_sync(0xffffffffu, cf,  o);
        }
        if (lane == 0) {
            int mode = 0;
            if (c8 == HID / NB) mode = 0;
            else if (c32 == HID / NB) mode = 1;
            else if (cf == HID / NB) mode = 2;
            g_maskmode = mode;
        }
    }
}

__device__ __forceinline__ bool mask_test(const void* mask, size_t off, int mode)
{
    if (mode == 0) return ((const unsigned char*)mask)[off] != 0;
    if (mode == 1) return ((const int*)mask)[off] != 0;
    return ((const float*)mask)[off] != 0.0f;
}

// warp-per-row ballot compaction; idx stored as smem BYTE offset
// L0: fp32 float2 layout, row stride 256B.  L1/L2: packed bf16x2, row stride 128B.
__global__ void k_compact_all(const void* m1, const float* w1, const float* b1, const float* tn1,
                              const void* m2, const float* w2, const float* b2, const float* tn2,
                              const void* m3, const float* w3, const float* b3, const float* tn3)
{
    int gw = (blockIdx.x * blockDim.x + threadIdx.x) >> 5;
    int lane = threadIdx.x & 31;
    if (gw >= 3 * ROWS) return;
    int L = gw / ROWS;
    int r = gw - L * ROWS;

    const void*  mask = (L == 0) ? m1 : (L == 1) ? m2 : m3;
    const float* w    = (L == 0) ? w1 : (L == 1) ? w2 : w3;
    const float* bias = (L == 0) ? b1 : (L == 1) ? b2 : b3;
    const float* tn   = (L == 0) ? tn1 : (L == 1) ? tn2 : tn3;
    float2* pk = (L == 0) ? (float2*)g_pk1 : (L == 1) ? (float2*)g_pk2 : (float2*)g_pk3;
    const int K   = (L == 0) ? IN : HID;
    const int J   = (L == 0) ? J1 : J2;
    const int mul = (L == 0) ? 256 : 128;

    float beta = 1.0f / (1.0f + expf(-tn[r]));
    float sc = 1.0f - beta;
    int mode = g_maskmode;

    int j = 0;
    for (int base = 0; base < K; base += 32) {
        int k = base + lane;
        bool on = (k < K) && mask_test(mask, (size_t)r * K + k, mode);
        unsigned bal = __ballot_sync(0xffffffffu, on);
        int pre = __popc(bal & ((1u << lane) - 1u));
        if (on && (j + pre) < J) {
            float2 p;
            p.x = w[(size_t)r * K + k] * sc;
            p.y = __int_as_float(k * mul);
            pk[(size_t)r * J + j + pre] = p;
        }
        j += __popc(bal);
    }
    if (j > J) j = J;
    for (int jj = j + lane; jj < J; jj += 32) {
        float2 p; p.x = 0.0f; p.y = __int_as_float(0);
        pk[(size_t)r * J + jj] = p;
    }
    if (lane == 0) {
        g_rowbias[L][r] = bias[r] * sc;
        g_rowbeta[L][r] = beta;
    }
}

// ---------------- persistent main kernel ----------------
// 128 CTAs x 512 threads. warp w: hl = w>>1 (h_local 0..7), nbh = w&1 (branch half).
// lane owns batches (2*lane, 2*lane+1).
// smem (floats): s_in[32768] | s_pk[8192] | s_l[1024] | s_spk[512] | s_wr[288]

template<int NF4>
__device__ __forceinline__ void pk_pf(uint32_t dst, const float4* src, int lane) {
    if (NF4 >= 64) {
        cp16(dst + lane * 16,       src + lane);
        cp16(dst + 512 + lane * 16, src + 32 + lane);
    } else {
        if (lane < NF4) cp16(dst + lane * 16, src + lane);
    }
}

template<int K, int J, bool PACKED, bool RD>
__device__ __forceinline__ void layer_step(
    int L, const float4* __restrict__ gstage, const float4* __restrict__ pk4,
    int cta, int w, int hl, int nbh, int lane,
    float* s, uint32_t s_in_u32, uint32_t s_pk_u32,
    float2* s_l, float* s_spk, const float* s_wr)
{
    const int tid = (w << 5) | lane;
    constexpr int nf4 = J / 2;
    constexpr int stage_f4 = PACKED ? (K * 8) : (K * 16);
    const int h = cta * HPC + hl;
    const int row0 = h * NB + nbh * 4;

    __syncthreads();                       // guard smem reuse from previous phase

    for (int i = tid; i < stage_f4; i += 512)
        cp16(s_in_u32 + i * 16, gstage + i);

    const uint32_t buf0 = s_pk_u32 + w * 1024;
    const uint32_t buf1 = s_pk_u32 + 16384 + w * 1024;
    pk_pf<nf4>(buf0, pk4 + (size_t)row0 * nf4, lane);
    CP_COMMIT();
    pk_pf<nf4>(buf1, pk4 + (size_t)(row0 + 1) * nf4, lane);
    CP_COMMIT();
    CP_WAIT1();
    __syncthreads();

    const char* sb = (const char*)s + lane * (PACKED ? 4 : 8);
    const float4* s_pkf = (const float4*)(s + 32768);
    float2 l2 = make_float2(0.f, 0.f);

    #pragma unroll
    for (int r = 0; r < 4; r++) {
        const int row = row0 + r;
        float2 dold = g_d[L][row * 32 + lane];
        const float4* p = s_pkf + (r & 1) * 1024 + w * 64;
        float bias = g_rowbias[L][row];
        float2 a0 = make_float2(bias, bias);
        float2 a1 = make_float2(0.f, 0.f);
        float2 a2 = make_float2(0.f, 0.f);
        float2 a3 = make_float2(0.f, 0.f);
        #pragma unroll 8
        for (int u = 0; u < nf4; u += 2) {
            float4 q  = p[u];
            float4 rr = p[u + 1];
            if (PACKED) {
                unsigned m0 = *(const unsigned*)(sb + __float_as_int(q.y));
                a0.x += q.x * __int_as_float(m0 << 16);
                a0.y += q.x * __int_as_float(m0 & 0xffff0000u);
                unsigned m1 = *(const unsigned*)(sb + __float_as_int(q.w));
                a1.x += q.z * __int_as_float(m1 << 16);
                a1.y += q.z * __int_as_float(m1 & 0xffff0000u);
                unsigned m2 = *(const unsigned*)(sb + __float_as_int(rr.y));
                a2.x += rr.x * __int_as_float(m2 << 16);
                a2.y += rr.x * __int_as_float(m2 & 0xffff0000u);
                unsigned m3 = *(const unsigned*)(sb + __float_as_int(rr.w));
                a3.x += rr.z * __int_as_float(m3 << 16);
                a3.y += rr.z * __int_as_float(m3 & 0xffff0000u);
            } else {
                float2 f0 = *(const float2*)(sb + __float_as_int(q.y));
                a0.x += q.x * f0.x;  a0.y += q.x * f0.y;
                float2 f1 = *(const float2*)(sb + __float_as_int(q.w));
                a1.x += q.z * f1.x;  a1.y += q.z * f1.y;
                float2 f2 = *(const float2*)(sb + __float_as_int(rr.y));
                a2.x += rr.x * f2.x; a2.y += rr.x * f2.y;
                float2 f3 = *(const float2*)(sb + __float_as_int(rr.w));
                a3.x += rr.z * f3.x; a3.y += rr.z * f3.y;
            }
        }
        float beta = g_rowbeta[L][row];
        float2 dd;
        dd.x = beta * dold.x + ((a0.x + a1.x) + (a2.x + a3.x));
        dd.y = beta * dold.y + ((a0.y + a1.y) + (a2.y + a3.y));
        g_d[L][row * 32 + lane] = dd;
        l2.x += dd.x; l2.y += dd.y;
        if (r + 2 < 4) {
            pk_pf<nf4>((r & 1) ? buf1 : buf0, pk4 + (size_t)(row0 + r + 2) * nf4, lane);
            CP_COMMIT();
        }
        if (r + 1 < 4) { if (r + 2 < 4) CP_WAIT1(); else CP_WAIT0(); }
    }

    s_l[((hl << 1) | nbh) * 32 + lane] = l2;
    __syncthreads();

    if (nbh == 0) {
        float2 lo = s_l[(hl << 1) * 32 + lane];
        float2 hi = s_l[((hl << 1) | 1) * 32 + lane];
        float2 l = make_float2(lo.x + hi.x, lo.y + hi.y);
        float a = g_alpha[L][h];
        float2 mo = g_mem[L][h * 32 + lane];
        float2 mn;
        mn.x = a * mo.x + (1.0f - a) * l.x - ((mo.x > VTH) ? 1.0f : 0.0f);
        mn.y = a * mo.y + (1.0f - a) * l.y - ((mo.y > VTH) ? 1.0f : 0.0f);
        g_mem[L][h * 32 + lane] = mn;
        if (!RD) {
            unsigned u = ((mn.x > VTH) ? 0x3F80u : 0u) | ((mn.y > VTH) ? 0x3F800000u : 0u);
            g_spkb[L][h * 32 + lane] = u;
        } else {
            s_spk[hl * 64 + 2 * lane]     = (mn.x > VTH) ? 1.0f : 0.0f;
            s_spk[hl * 64 + 2 * lane + 1] = (mn.y > VTH) ? 1.0f : 0.0f;
        }
    }

    if (RD) {
        __syncthreads();
        for (int i = tid; i < OUT * B; i += 512) {
            int o = i >> 6, b = i & 63;
            float r = 0.f;
            #pragma unroll
            for (int hh = 0; hh < HPC; hh++)
                r += s_wr[o * HPC + hh] * s_spk[hh * 64 + b];
            g_rd[cta * (OUT * B) + i] = r;
        }
    }
}

__device__ __forceinline__ void mr_update(const float* __restrict__ br, int cta, int tid)
{
    int idx = cta * 512 + tid;
    if (idx < OUT * B) {
        int o = idx >> 6;
        float sum = br[o];
        #pragma unroll 16
        for (int c = 0; c < NCTA; c++) sum += ldcv(&g_rd[c * (OUT * B) + idx]);
        float ar = g_alphar[o];
        float m = ar * g_mr[idx] + (1.0f - ar) * sum;
        g_mr[idx] = m;
        g_acc[idx] += m;
    }
}

__global__ void __launch_bounds__(512, 1) k_main(const float* __restrict__ wr,
                                                 const float* __restrict__ br,
                                                 float* __restrict__ out)
{
    extern __shared__ float s[];
    float2* s_l  = (float2*)(s + 32768 + 8192);        // 512 float2
    float*  s_spk = s + 32768 + 8192 + 1024;           // 512
    float*  s_wr  = s + 32768 + 8192 + 1024 + 512;     // 288
    const uint32_t s_in_u32 = (uint32_t)__cvta_generic_to_shared(s);
    const uint32_t s_pk_u32 = (uint32_t)__cvta_generic_to_shared(s + 32768);

    const int tid = threadIdx.x, lane = tid & 31, w = tid >> 5;
    const int hl = w >> 1, nbh = w & 1;
    const int cta = blockIdx.x;
    unsigned nbar = 0;

    // stage wr chunk (constant across steps)
    for (int i = tid; i < OUT * HPC; i += 512) {
        int o = i / HPC, hh = i % HPC;
        s_wr[i] = wr[o * HID + cta * HPC + hh];
    }

    layer_step<IN, J1, false, false>(0, (const float4*)g_xT, g_pk1,
        cta, w, hl, nbh, lane, s, s_in_u32, s_pk_u32, s_l, s_spk, s_wr);
    gsync(NCTA * (++nbar));

    for (int t = 0; t < T; t++) {
        layer_step<HID, J2, true, false>(1, (const float4*)g_spkb[0], g_pk2,
            cta, w, hl, nbh, lane, s, s_in_u32, s_pk_u32, s_l, s_spk, s_wr);
        if (t > 0) mr_update(br, cta, tid);
        gsync(NCTA * (++nbar));

        layer_step<HID, J2, true, true>(2, (const float4*)g_spkb[1], g_pk3,
            cta, w, hl, nbh, lane, s, s_in_u32, s_pk_u32, s_l, s_spk, s_wr);
        if (t + 1 < T)
            layer_step<IN, J1, false, false>(0, (const float4*)((const float*)g_xT + (size_t)(t + 1) * IN * 64), g_pk1,
                cta, w, hl, nbh, lane, s, s_in_u32, s_pk_u32, s_l, s_spk, s_wr);
        gsync(NCTA * (++nbar));
    }

    mr_update(br, cta, tid);
    gsync(NCTA * (++nbar));

    if (cta == 0 && tid < B) {
        int b = tid;
        float v[OUT];
        float mx = -1e30f;
        #pragma unroll
        for (int o = 0; o < OUT; o++) {
            v[o] = ldcv(&g_acc[o * 64 + b]) / (float)T;
            mx = fmaxf(mx, v[o]);
        }
        float sum = 0.0f;
        #pragma unroll
        for (int o = 0; o < OUT; o++) sum += expf(v[o] - mx);
        float ls = logf(sum);
        #pragma unroll
        for (int o = 0; o < OUT; o++) out[b * OUT + o] = v[o] - mx - ls;
    }
}

// ---------------- launch ----------------
extern "C" void kernel_launch(void* const* d_in, const int* in_sizes, int n_in,
                              void* d_out, int out_size)
{
    const float* x   = (const float*)d_in[0];
    const float* w1  = (const float*)d_in[1];
    const float* b1  = (const float*)d_in[2];
    const float* tm1 = (const float*)d_in[3];
    const float* tn1 = (const float*)d_in[4];
    const float* w2  = (const float*)d_in[5];
    const float* b2  = (const float*)d_in[6];
    const float* tm2 = (const float*)d_in[7];
    const float* tn2 = (const float*)d_in[8];
    const float* w3  = (const float*)d_in[9];
    const float* b3  = (const float*)d_in[10];
    const float* tm3 = (const float*)d_in[11];
    const float* tn3 = (const float*)d_in[12];
    const float* wr  = (const float*)d_in[13];
    const float* br  = (const float*)d_in[14];
    const float* tmr = (const float*)d_in[15];
    const void*  m1  = d_in[16];
    const void*  m2  = d_in[17];
    const void*  m3  = d_in[18];

    const int SMEM_MAIN = (32768 + 8192 + 1024 + 512 + 288) * 4;   // 171136 B
    cudaFuncSetAttribute(k_main, cudaFuncAttributeMaxDynamicSharedMemorySize, SMEM_MAIN);

    k_pre<<<3072, 256>>>(x, tm1, tm2, tm3, tmr, m2);
    k_compact_all<<<3072, 256>>>(m1, w1, b1, tn1, m2, w2, b2, tn2, m3, w3, b3, tn3);
    k_main<<<NCTA, 512, SMEM_MAIN>>>(wr, br, (float*)d_out);
}

// round 5
// speedup vs baseline: 3.7540x; 1.0106x over previous
#include <cuda_runtime.h>
#include <math.h>
#include <stdint.h>

#define B     64
#define T     150
#define IN    120
#define HID   1024
#define NB    8
#define ROWS  8192
#define OUT   35
#define J1    16
#define J2    128
#define VTH   1.0f
#define NCTA  128
#define HPC   8

// ---------------- device global scratch ----------------
__device__ __align__(128) float4  g_pk1[ROWS * (J1/2)];
__device__ __align__(128) float4  g_pk2[ROWS * (J2/2)];
__device__ __align__(128) float4  g_pk3[ROWS * (J2/2)];
__device__ float   g_rowbias[3][ROWS];
__device__ float   g_rowbeta[3][ROWS];
__device__ float   g_alpha[3][HID];
__device__ float   g_alphar[OUT];
__device__ __align__(128) float2  g_xT[T * IN * 32];     // [t][k][lane]
__device__ float2  g_d[3][ROWS * 32];
__device__ float2  g_mem[3][HID * 32];
__device__ __align__(128) unsigned g_spkw[2][HID * 32];  // packed bf16x2 spikes
__device__ float   g_rd[NCTA * OUT * B];
__device__ float   g_mr[OUT * B];
__device__ float   g_acc[OUT * B];
__device__ int     g_maskmode;
__device__ unsigned g_bar_cnt;

// smem layout (float units)
#define OFF_IN   0          // 32768 floats: staged spikes (or x overlay)
#define OFF_PK   32768      // 16384 floats: current big-layer pk block (64KB)
#define OFF_PK1  49152      // 2048 floats: resident L1 pk block (8KB)
#define OFF_L    51200      // 1024 floats (512 float2)
#define OFF_SPK  52224      // 512 floats
#define OFF_WR   52736      // 288 floats
#define OFF_MB   53024      // 3 mbarriers (8B each) -> 6 floats + pad
#define SMEM_FLOATS (53024 + 8)

// ---------------- helpers ----------------
__device__ __forceinline__ void cp16(uint32_t dst, const void* src) {
    asm volatile("cp.async.cg.shared.global [%0], [%1], 16;" :: "r"(dst), "l"(src));
}
#define CP_COMMIT() asm volatile("cp.async.commit_group;" ::: "memory")
#define CP_WAIT0()  asm volatile("cp.async.wait_group 0;" ::: "memory")

__device__ __forceinline__ float ldcv(const float* p) {
    float v; asm volatile("ld.global.cv.f32 %0, [%1];" : "=f"(v) : "l"(p)); return v;
}

__device__ __forceinline__ void mbar_init(uint32_t mbar, unsigned cnt) {
    asm volatile("mbarrier.init.shared::cta.b64 [%0], %1;" :: "r"(mbar), "r"(cnt) : "memory");
}
__device__ __forceinline__ void mbar_expect(uint32_t mbar, unsigned bytes) {
    asm volatile("mbarrier.arrive.expect_tx.shared::cta.b64 _, [%0], %1;"
                 :: "r"(mbar), "r"(bytes) : "memory");
}
__device__ __forceinline__ void mbar_wait(uint32_t mbar, unsigned ph) {
    asm volatile(
        "{\n\t"
        ".reg .pred P;\n\t"
        "W%=:\n\t"
        "mbarrier.try_wait.parity.shared::cta.b64 P, [%0], %1;\n\t"
        "@!P bra W%=;\n\t"
        "}"
        :: "r"(mbar), "r"(ph) : "memory");
}
__device__ __forceinline__ void tma_bulk(uint32_t dst, const void* src, unsigned bytes, uint32_t mbar) {
    asm volatile("cp.async.bulk.shared::cta.global.mbarrier::complete_tx::bytes [%0], [%1], %2, [%3];"
                 :: "r"(dst), "l"(src), "r"(bytes), "r"(mbar) : "memory");
}
#define FENCE_ASYNC() asm volatile("fence.proxy.async;" ::: "memory")

__device__ __forceinline__ void gsync(unsigned target) {
    __syncthreads();
    if (threadIdx.x == 0) {
        asm volatile("red.release.gpu.global.add.u32 [%0], %1;"
                     :: "l"(&g_bar_cnt), "r"(1u) : "memory");
        unsigned v;
        do {
            asm volatile("ld.acquire.gpu.global.u32 %0, [%1];"
                         : "=r"(v) : "l"(&g_bar_cnt) : "memory");
        } while (v < target);
    }
    __syncthreads();
}

// ---------------- preprocessing ----------------
__global__ void k_pre(const float* __restrict__ x,
                      const float* tm1, const float* tm2, const float* tm3, const float* tmr,
                      const void* mask2)
{
    int i = blockIdx.x * blockDim.x + threadIdx.x;
    if (i == 0) g_bar_cnt = 0u;
    if (i < 3 * ROWS * 32) (&g_d[0][0])[i] = make_float2(0.f, 0.f);
    if (i < 3 * HID * 32)  (&g_mem[0][0])[i] = make_float2(0.f, 0.f);
    if (i < OUT * B) { g_mr[i] = 0.f; g_acc[i] = 0.f; }
    if (i < T * IN * 64) {
        int c = i & 1, lane = (i >> 1) & 31, tk = i >> 6;
        int k = tk % IN, t = tk / IN;
        int b = 2 * lane + c;
        ((float*)g_xT)[i] = x[((size_t)b * T + t) * IN + k];
    }
    if (i < HID)            g_alpha[0][i]         = 1.0f / (1.0f + expf(-tm1[i]));
    else if (i < 2*HID)     g_alpha[1][i - HID]   = 1.0f / (1.0f + expf(-tm2[i - HID]));
    else if (i < 3*HID)     g_alpha[2][i - 2*HID] = 1.0f / (1.0f + expf(-tm3[i - 2*HID]));
    else if (i < 3*HID+OUT) g_alphar[i - 3*HID]   = 1.0f / (1.0f + expf(-tmr[i - 3*HID]));
    if (blockIdx.x == 0 && threadIdx.x < 32) {
        int lane = threadIdx.x;
        const unsigned char* p8  = (const unsigned char*)mask2;
        const int*           p32 = (const int*)mask2;
        const float*         pf  = (const float*)mask2;
        int c8 = 0, c32 = 0, cf = 0;
        for (int k = lane; k < HID; k += 32) {
            c8  += (p8[k]  != 0);
            c32 += (p32[k] != 0);
            cf  += (pf[k]  != 0.0f);
        }
        #pragma unroll
        for (int o = 16; o > 0; o >>= 1) {
            c8  += __shfl_xor_sync(0xffffffffu, c8,  o);
            c32 += __shfl_xor_sync(0xffffffffu, c32, o);
            cf  += __shfl_xor_sync(0xffffffffu, cf,  o);
        }
        if (lane == 0) {
            int mode = 0;
            if (c8 == HID / NB) mode = 0;
            else if (c32 == HID / NB) mode = 1;
            else if (cf == HID / NB) mode = 2;
            g_maskmode = mode;
        }
    }
}

__device__ __forceinline__ bool mask_test(const void* mask, size_t off, int mode)
{
    if (mode == 0) return ((const unsigned char*)mask)[off] != 0;
    if (mode == 1) return ((const int*)mask)[off] != 0;
    return ((const float*)mask)[off] != 0.0f;
}

__global__ void k_compact_all(const void* m1, const float* w1, const float* b1, const float* tn1,
                              const void* m2, const float* w2, const float* b2, const float* tn2,
                              const void* m3, const float* w3, const float* b3, const float* tn3)
{
    int gw = (blockIdx.x * blockDim.x + threadIdx.x) >> 5;
    int lane = threadIdx.x & 31;
    if (gw >= 3 * ROWS) return;
    int L = gw / ROWS;
    int r = gw - L * ROWS;

    const void*  mask = (L == 0) ? m1 : (L == 1) ? m2 : m3;
    const float* w    = (L == 0) ? w1 : (L == 1) ? w2 : w3;
    const float* bias = (L == 0) ? b1 : (L == 1) ? b2 : b3;
    const float* tn   = (L == 0) ? tn1 : (L == 1) ? tn2 : tn3;
    float2* pk = (L == 0) ? (float2*)g_pk1 : (L == 1) ? (float2*)g_pk2 : (float2*)g_pk3;
    const int K   = (L == 0) ? IN : HID;
    const int J   = (L == 0) ? J1 : J2;
    const int mul = (L == 0) ? 256 : 128;     // byte offset scale into staged input

    float beta = 1.0f / (1.0f + expf(-tn[r]));
    float sc = 1.0f - beta;
    int mode = g_maskmode;

    int j = 0;
    for (int base = 0; base < K; base += 32) {
        int k = base + lane;
        bool on = (k < K) && mask_test(mask, (size_t)r * K + k, mode);
        unsigned bal = __ballot_sync(0xffffffffu, on);
        int pre = __popc(bal & ((1u << lane) - 1u));
        if (on && (j + pre) < J) {
            float2 p;
            p.x = w[(size_t)r * K + k] * sc;
            p.y = __int_as_float(k * mul);
            pk[(size_t)r * J + j + pre] = p;
        }
        j += __popc(bal);
    }
    if (j > J) j = J;
    for (int jj = j + lane; jj < J; jj += 32) {
        float2 p; p.x = 0.0f; p.y = __int_as_float(0);
        pk[(size_t)r * J + jj] = p;
    }
    if (lane == 0) {
        g_rowbias[L][r] = bias[r] * sc;
        g_rowbeta[L][r] = beta;
    }
}

// ---------------- main kernel compute pieces ----------------
// warp w: hl = w>>1 (h_local), nbh = w&1 (branch half); lane owns batches (2lane, 2lane+1)

template<int NF4, bool PACKED, bool RD>
__device__ __forceinline__ void layer_compute(
    int L, int cta, int hl, int nbh, int lane,
    const float* s, const float4* s_pkblk,
    float2* s_l, float* s_spk, const float* s_wr)
{
    const int tid = (((hl << 1) | nbh) << 5) | lane;
    const int h = cta * HPC + hl;
    const int row0 = h * NB + nbh * 4;
    const int lrow0 = hl * 8 + nbh * 4;
    const char* sb = (const char*)s + lane * (PACKED ? 4 : 8);
    float2 l2 = make_float2(0.f, 0.f);

    #pragma unroll
    for (int r = 0; r < 4; r++) {
        const int row = row0 + r;
        float2 dold = g_d[L][row * 32 + lane];
        const float4* p = s_pkblk + (lrow0 + r) * NF4;
        float bias = g_rowbias[L][row];
        float2 a0 = make_float2(bias, bias);
        float2 a1 = make_float2(0.f, 0.f);
        float2 a2 = make_float2(0.f, 0.f);
        float2 a3 = make_float2(0.f, 0.f);
        #pragma unroll 8
        for (int u = 0; u < NF4; u += 2) {
            float4 q  = p[u];
            float4 rr = p[u + 1];
            if (PACKED) {
                unsigned m0 = *(const unsigned*)(sb + __float_as_int(q.y));
                a0.x += q.x * __int_as_float(m0 << 16);
                a0.y += q.x * __int_as_float(m0 & 0xffff0000u);
                unsigned m1 = *(const unsigned*)(sb + __float_as_int(q.w));
                a1.x += q.z * __int_as_float(m1 << 16);
                a1.y += q.z * __int_as_float(m1 & 0xffff0000u);
                unsigned m2 = *(const unsigned*)(sb + __float_as_int(rr.y));
                a2.x += rr.x * __int_as_float(m2 << 16);
                a2.y += rr.x * __int_as_float(m2 & 0xffff0000u);
                unsigned m3 = *(const unsigned*)(sb + __float_as_int(rr.w));
                a3.x += rr.z * __int_as_float(m3 << 16);
                a3.y += rr.z * __int_as_float(m3 & 0xffff0000u);
            } else {
                float2 f0 = *(const float2*)(sb + __float_as_int(q.y));
                a0.x += q.x * f0.x;  a0.y += q.x * f0.y;
                float2 f1 = *(const float2*)(sb + __float_as_int(q.w));
                a1.x += q.z * f1.x;  a1.y += q.z * f1.y;
                float2 f2 = *(const float2*)(sb + __float_as_int(rr.y));
                a2.x += rr.x * f2.x; a2.y += rr.x * f2.y;
                float2 f3 = *(const float2*)(sb + __float_as_int(rr.w));
                a3.x += rr.z * f3.x; a3.y += rr.z * f3.y;
            }
        }
        float beta = g_rowbeta[L][row];
        float2 dd;
        dd.x = beta * dold.x + ((a0.x + a1.x) + (a2.x + a3.x));
        dd.y = beta * dold.y + ((a0.y + a1.y) + (a2.y + a3.y));
        g_d[L][row * 32 + lane] = dd;
        l2.x += dd.x; l2.y += dd.y;
    }

    s_l[((hl << 1) | nbh) * 32 + lane] = l2;
    __syncthreads();

    if (nbh == 0) {
        float2 lo = s_l[(hl << 1) * 32 + lane];
        float2 hi = s_l[((hl << 1) | 1) * 32 + lane];
        float2 l = make_float2(lo.x + hi.x, lo.y + hi.y);
        float a = g_alpha[L][h];
        float2 mo = g_mem[L][h * 32 + lane];
        float2 mn;
        mn.x = a * mo.x + (1.0f - a) * l.x - ((mo.x > VTH) ? 1.0f : 0.0f);
        mn.y = a * mo.y + (1.0f - a) * l.y - ((mo.y > VTH) ? 1.0f : 0.0f);
        g_mem[L][h * 32 + lane] = mn;
        if (!RD) {
            unsigned u = ((mn.x > VTH) ? 0x3F80u : 0u) | ((mn.y > VTH) ? 0x3F800000u : 0u);
            g_spkw[L][h * 32 + lane] = u;
        } else {
            s_spk[hl * 64 + 2 * lane]     = (mn.x > VTH) ? 1.0f : 0.0f;
            s_spk[hl * 64 + 2 * lane + 1] = (mn.y > VTH) ? 1.0f : 0.0f;
        }
    }

    if (RD) {
        __syncthreads();
        for (int i = tid; i < OUT * B; i += 512) {
            int o = i >> 6, b = i & 63;
            float r = 0.f;
            #pragma unroll
            for (int hh = 0; hh < HPC; hh++)
                r += s_wr[o * HPC + hh] * s_spk[hh * 64 + b];
            g_rd[cta * (OUT * B) + i] = r;
        }
    }
}

__device__ __forceinline__ void mr_update(const float* __restrict__ br, int cta, int tid)
{
    int idx = cta * 512 + tid;
    if (idx < OUT * B) {
        int o = idx >> 6;
        float sum = br[o];
        #pragma unroll 16
        for (int c = 0; c < NCTA; c++) sum += ldcv(&g_rd[c * (OUT * B) + idx]);
        float ar = g_alphar[o];
        float m = ar * g_mr[idx] + (1.0f - ar) * sum;
        g_mr[idx] = m;
        g_acc[idx] += m;
    }
}

__global__ void __launch_bounds__(512, 1) k_main(const float* __restrict__ wr,
                                                 const float* __restrict__ br,
                                                 float* __restrict__ out)
{
    extern __shared__ float s[];
    float*  s_in  = s + OFF_IN;
    const float4* s_pk  = (const float4*)(s + OFF_PK);
    const float4* s_pk1 = (const float4*)(s + OFF_PK1);
    float2* s_l   = (float2*)(s + OFF_L);
    float*  s_spk = s + OFF_SPK;
    float*  s_wr  = s + OFF_WR;
    const uint32_t u_in  = (uint32_t)__cvta_generic_to_shared(s + OFF_IN);
    const uint32_t u_pk  = (uint32_t)__cvta_generic_to_shared(s + OFF_PK);
    const uint32_t u_pk1 = (uint32_t)__cvta_generic_to_shared(s + OFF_PK1);
    const uint32_t mb0 = (uint32_t)__cvta_generic_to_shared(s + OFF_MB);      // spikes
    const uint32_t mb1 = mb0 + 8;                                             // pk
    const uint32_t mb2 = mb0 + 16;                                            // x

    const int tid = threadIdx.x, lane = tid & 31, w = tid >> 5;
    const int hl = w >> 1, nbh = w & 1;
    const int cta = blockIdx.x;
    unsigned nbar = 0;
    unsigned ph_in = 0, ph_pk = 0, ph_x = 0;

    // ---- prologue ----
    if (tid == 0) { mbar_init(mb0, 1); mbar_init(mb1, 1); mbar_init(mb2, 1); }
    // resident L1 pk block (8KB) + wr chunk
    cp16(u_pk1 + tid * 16, g_pk1 + (size_t)cta * 512 + tid);
    CP_COMMIT();
    for (int i = tid; i < OUT * HPC; i += 512) {
        int o = i / HPC, hh = i % HPC;
        s_wr[i] = wr[o * HID + cta * HPC + hh];
    }
    __syncthreads();
    if (tid == 0) {
        FENCE_ASYNC();
        mbar_expect(mb2, IN * 64 * 4);
        tma_bulk(u_in, (const char*)g_xT, IN * 64 * 4, mb2);
    }
    CP_WAIT0();
    __syncthreads();
    mbar_wait(mb2, ph_x); ph_x ^= 1;
    layer_compute<J1/2, false, false>(0, cta, hl, nbh, lane, s_in, s_pk1, s_l, s_spk, s_wr);
    gsync(NCTA * (++nbar));

    for (int t = 0; t < T; t++) {
        // ---- phase A: L2(t) ----
        if (tid == 0) {
            FENCE_ASYNC();
            mbar_expect(mb0, HID * 32 * 4);
            tma_bulk(u_in, (const char*)g_spkw[0], HID * 32 * 4, mb0);
            mbar_expect(mb1, 65536);
            tma_bulk(u_pk, (const char*)g_pk2 + (size_t)cta * 65536, 65536, mb1);
        }
        if (t > 0) mr_update(br, cta, tid);
        mbar_wait(mb0, ph_in); ph_in ^= 1;
        mbar_wait(mb1, ph_pk); ph_pk ^= 1;
        layer_compute<J2/2, true, false>(1, cta, hl, nbh, lane, s_in, s_pk, s_l, s_spk, s_wr);
        gsync(NCTA * (++nbar));

        // ---- phase B: L3(t) + L1(t+1) ----
        if (tid == 0) {
            FENCE_ASYNC();
            mbar_expect(mb0, HID * 32 * 4);
            tma_bulk(u_in, (const char*)g_spkw[1], HID * 32 * 4, mb0);
            mbar_expect(mb1, 65536);
            tma_bulk(u_pk, (const char*)g_pk3 + (size_t)cta * 65536, 65536, mb1);
        }
        mbar_wait(mb0, ph_in); ph_in ^= 1;
        mbar_wait(mb1, ph_pk); ph_pk ^= 1;
        layer_compute<J2/2, true, true>(2, cta, hl, nbh, lane, s_in, s_pk, s_l, s_spk, s_wr);
        __syncthreads();   // all warps done reading s_in before x overlay
        if (t + 1 < T) {
            if (tid == 0) {
                FENCE_ASYNC();
                mbar_expect(mb2, IN * 64 * 4);
                tma_bulk(u_in, (const char*)g_xT + (size_t)(t + 1) * IN * 64 * 4, IN * 64 * 4, mb2);
            }
            mbar_wait(mb2, ph_x); ph_x ^= 1;
            layer_compute<J1/2, false, false>(0, cta, hl, nbh, lane, s_in, s_pk1, s_l, s_spk, s_wr);
        }
        gsync(NCTA * (++nbar));
    }

    mr_update(br, cta, tid);
    gsync(NCTA * (++nbar));

    if (cta == 0 && tid < B) {
        int b = tid;
        float v[OUT];
        float mx = -1e30f;
        #pragma unroll
        for (int o = 0; o < OUT; o++) {
            v[o] = ldcv(&g_acc[o * 64 + b]) / (float)T;
            mx = fmaxf(mx, v[o]);
        }
        float sum = 0.0f;
        #pragma unroll
        for (int o = 0; o < OUT; o++) sum += expf(v[o] - mx);
        float ls = logf(sum);
        #pragma unroll
        for (int o = 0; o < OUT; o++) out[b * OUT + o] = v[o] - mx - ls;
    }
}

// ---------------- launch ----------------
extern "C" void kernel_launch(void* const* d_in, const int* in_sizes, int n_in,
                              void* d_out, int out_size)
{
    const float* x   = (const float*)d_in[0];
    const float* w1  = (const float*)d_in[1];
    const float* b1  = (const float*)d_in[2];
    const float* tm1 = (const float*)d_in[3];
    const float* tn1 = (const float*)d_in[4];
    const float* w2  = (const float*)d_in[5];
    const float* b2  = (const float*)d_in[6];
    const float* tm2 = (const float*)d_in[7];
    const float* tn2 = (const float*)d_in[8];
    const float* w3  = (const float*)d_in[9];
    const float* b3  = (const float*)d_in[10];
    const float* tm3 = (const float*)d_in[11];
    const float* tn3 = (const float*)d_in[12];
    const float* wr  = (const float*)d_in[13];
    const float* br  = (const float*)d_in[14];
    const float* tmr = (const float*)d_in[15];
    const void*  m1  = d_in[16];
    const void*  m2  = d_in[17];
    const void*  m3  = d_in[18];

    const int SMEM_MAIN = SMEM_FLOATS * 4;   // ~212 KB
    cudaFuncSetAttribute(k_main, cudaFuncAttributeMaxDynamicSharedMemorySize, SMEM_MAIN);

    k_pre<<<3072, 256>>>(x, tm1, tm2, tm3, tmr, m2);
    k_compact_all<<<3072, 256>>>(m1, w1, b1, tn1, m2, w2, b2, tn2, m3, w3, b3, tn3);
    k_main<<<NCTA, 512, SMEM_MAIN>>>(wr, br, (float*)d_out);
}